// round 6
// baseline (speedup 1.0000x reference)
#include <cuda_runtime.h>
#include <cuda_bf16.h>
#include <cstdint>
#include <cstddef>

// ---------------------------------------------------------------------------
// HeteroSAGEAttention on GB300 — round 6 (= round-4 design; broker timed out
// twice before it ever ran; resubmitted unchanged after repeated audit)
//   tcgen05 is unavailable in this harness (PTX target is compute_103, not
//   sm_103a). Standard-PTX tensor path instead:
//   * GEMMs via mma.sync.m16n8k16 bf16 with 2-term split (3 MMA passes:
//     Ah*Bh + Ah*Bl + Al*Bh) => ~1e-5 accuracy, tensor-pipe throughput
//   * attention score fused into GEMM epilogue (no separate score kernels)
//   * edge scatter: red.global.add.v4.f32 warp-per-edge
// ---------------------------------------------------------------------------

#define NN 100000
#define HH 128
#define EE 500000
#define NH (NN * HH)

// scratch: 8 node-feature buffers + 6 scalar-per-node + split weights (bf16)
#define WT_FLOATS 229376ull
__device__ __align__(16) float g_scratch[8ull * NH + 6ull * NN + WT_FLOATS];

// ---------------------------------------------------------------------------
__device__ __forceinline__ void mma16816(float* c, uint32_t a0, uint32_t a1,
                                         uint32_t a2, uint32_t a3,
                                         uint32_t b0, uint32_t b1) {
    asm volatile(
        "mma.sync.aligned.m16n8k16.row.col.f32.bf16.bf16.f32 "
        "{%0,%1,%2,%3}, {%4,%5,%6,%7}, {%8,%9}, {%0,%1,%2,%3};"
        : "+f"(c[0]), "+f"(c[1]), "+f"(c[2]), "+f"(c[3])
        : "r"(a0), "r"(a1), "r"(a2), "r"(a3), "r"(b0), "r"(b1));
}

// ---------------------------------------------------------------------------
// prep_w: split + transpose weights to bf16.
//   th[n*K+k] = bf16(W[k*N+n]);  tl[n*K+k] = bf16(W[k*N+n] - th)
// ---------------------------------------------------------------------------
__global__ void prep_w_kernel(const float* __restrict__ W,
                              __nv_bfloat16* __restrict__ th,
                              __nv_bfloat16* __restrict__ tl, int K, int N) {
    int o = blockIdx.x * blockDim.x + threadIdx.x;
    if (o >= K * N) return;
    int n = o / K, k = o % K;
    float v = __ldg(W + (size_t)k * N + n);
    __nv_bfloat16 h = __float2bfloat16(v);
    th[o] = h;
    tl[o] = __float2bfloat16(v - __bfloat162float(h));
}

// ---------------------------------------------------------------------------
// GEMM: C[M x N_] = A[M x KTOT] @ Bt^T  (Bt pre-split bf16 [N_, KTOT]).
// 128 rows per CTA, 256 threads = 4(m) x 2(n) warps, warp tile 32 x N_/2.
// 3 bf16 passes. Optional fused score s[m] = C[m,:].avec; optional bias.
// ---------------------------------------------------------------------------
template <int N_, int KTOT, bool SCORE, bool BIAS>
__global__ __launch_bounds__(256, 1) void gemm_mma(
    const float* __restrict__ A, const __nv_bfloat16* __restrict__ Bh,
    const __nv_bfloat16* __restrict__ Bl, const float* __restrict__ bias,
    const float* __restrict__ avec, float* __restrict__ C,
    float* __restrict__ sout, int M)
{
    constexpr int SA = KTOT + 8;          // padded smem stride (bf16 elems)
    constexpr int WN = N_ / 2;            // warp n-extent
    constexpr int NJ = WN / 8;            // n-subtiles per warp

    extern __shared__ char smem[];
    __nv_bfloat16* sAh = (__nv_bfloat16*)smem;
    __nv_bfloat16* sAl = sAh + 128 * SA;
    __nv_bfloat16* sBh = sAl + 128 * SA;
    __nv_bfloat16* sBl = sBh + N_ * SA;
    float* s_red = (float*)(sBl + N_ * SA);   // [128]

    const int tid  = threadIdx.x;
    const int wid  = tid >> 5;
    const int lane = tid & 31;
    const int wm   = wid & 3;             // 0..3
    const int wn   = wid >> 2;            // 0..1
    const int q    = lane & 3;
    const int nr   = lane >> 2;
    const int m0   = blockIdx.x * 128;

    if (SCORE && tid < 128) s_red[tid] = 0.f;

    // ---- load A (fp32), split into bf16 hi/lo in smem ----
    for (int i = tid; i < 128 * (KTOT / 4); i += 256) {
        int r  = i / (KTOT / 4);
        int c4 = (i % (KTOT / 4)) * 4;
        float4 v = make_float4(0.f, 0.f, 0.f, 0.f);
        if (m0 + r < M)
            v = __ldg((const float4*)(A + (size_t)(m0 + r) * KTOT + c4));
        __nv_bfloat16 hx = __float2bfloat16(v.x);
        __nv_bfloat16 hy = __float2bfloat16(v.y);
        __nv_bfloat16 hz = __float2bfloat16(v.z);
        __nv_bfloat16 hw = __float2bfloat16(v.w);
        __nv_bfloat162* ph = (__nv_bfloat162*)&sAh[r * SA + c4];
        __nv_bfloat162* pl = (__nv_bfloat162*)&sAl[r * SA + c4];
        ph[0] = __nv_bfloat162(hx, hy);
        ph[1] = __nv_bfloat162(hz, hw);
        pl[0] = __nv_bfloat162(__float2bfloat16(v.x - __bfloat162float(hx)),
                               __float2bfloat16(v.y - __bfloat162float(hy)));
        pl[1] = __nv_bfloat162(__float2bfloat16(v.z - __bfloat162float(hz)),
                               __float2bfloat16(v.w - __bfloat162float(hw)));
    }
    // ---- load pre-split B halves (bf16, [N_, KTOT] row-major) ----
    for (int i = tid; i < N_ * (KTOT / 8); i += 256) {
        int r  = i / (KTOT / 8);
        int c8 = (i % (KTOT / 8)) * 8;
        *(uint4*)&sBh[r * SA + c8] = __ldg((const uint4*)(Bh + (size_t)r * KTOT + c8));
        *(uint4*)&sBl[r * SA + c8] = __ldg((const uint4*)(Bl + (size_t)r * KTOT + c8));
    }
    __syncthreads();

    // ---- accumulate: 3 passes (Ah*Bh, Ah*Bl, Al*Bh) ----
    float acc[2][NJ][4];
#pragma unroll
    for (int s = 0; s < 2; s++)
#pragma unroll
        for (int j = 0; j < NJ; j++)
#pragma unroll
            for (int e = 0; e < 4; e++) acc[s][j][e] = 0.f;

    const __nv_bfloat16* Ap[3] = {sAh, sAh, sAl};
    const __nv_bfloat16* Bp[3] = {sBh, sBl, sBh};
#pragma unroll
    for (int p = 0; p < 3; p++) {
        const __nv_bfloat16* a_s = Ap[p];
        const __nv_bfloat16* b_s = Bp[p];
#pragma unroll
        for (int k0 = 0; k0 < KTOT; k0 += 16) {
            uint32_t bf[NJ][2];
#pragma unroll
            for (int j = 0; j < NJ; j++) {
                int n = wn * WN + j * 8 + nr;
                bf[j][0] = *(const uint32_t*)&b_s[n * SA + k0 + q * 2];
                bf[j][1] = *(const uint32_t*)&b_s[n * SA + k0 + 8 + q * 2];
            }
#pragma unroll
            for (int sm = 0; sm < 2; sm++) {
                int m = wm * 32 + sm * 16 + nr;
                uint32_t a0 = *(const uint32_t*)&a_s[m * SA + k0 + q * 2];
                uint32_t a1 = *(const uint32_t*)&a_s[(m + 8) * SA + k0 + q * 2];
                uint32_t a2 = *(const uint32_t*)&a_s[m * SA + k0 + 8 + q * 2];
                uint32_t a3 = *(const uint32_t*)&a_s[(m + 8) * SA + k0 + 8 + q * 2];
#pragma unroll
                for (int j = 0; j < NJ; j++)
                    mma16816(acc[sm][j], a0, a1, a2, a3, bf[j][0], bf[j][1]);
            }
        }
    }

    // ---- fused score: s[m] = sum_n C[m][n] * avec[n] ----
    if (SCORE) {
        float part[2][2];
        part[0][0] = part[0][1] = part[1][0] = part[1][1] = 0.f;
#pragma unroll
        for (int sm = 0; sm < 2; sm++)
#pragma unroll
            for (int j = 0; j < NJ; j++) {
                int n = wn * WN + j * 8 + q * 2;
                float av0 = __ldg(avec + n), av1 = __ldg(avec + n + 1);
                part[sm][0] = fmaf(acc[sm][j][0], av0, fmaf(acc[sm][j][1], av1, part[sm][0]));
                part[sm][1] = fmaf(acc[sm][j][2], av0, fmaf(acc[sm][j][3], av1, part[sm][1]));
            }
#pragma unroll
        for (int sm = 0; sm < 2; sm++)
#pragma unroll
            for (int h = 0; h < 2; h++) {
                float v = part[sm][h];
                v += __shfl_xor_sync(0xffffffffu, v, 1);
                v += __shfl_xor_sync(0xffffffffu, v, 2);
                if (q == 0)
                    atomicAdd(&s_red[wm * 32 + sm * 16 + nr + h * 8], v);
            }
    }

    // ---- store C (+bias) ----
#pragma unroll
    for (int sm = 0; sm < 2; sm++) {
        int m = wm * 32 + sm * 16 + nr;
#pragma unroll
        for (int j = 0; j < NJ; j++) {
            int gn = wn * WN + j * 8 + q * 2;
            float b0 = 0.f, b1 = 0.f;
            if (BIAS) { b0 = __ldg(bias + gn); b1 = __ldg(bias + gn + 1); }
            if (m0 + m < M) {
                float2 r0 = make_float2(acc[sm][j][0] + b0, acc[sm][j][1] + b1);
                *(float2*)(C + (size_t)(m0 + m) * N_ + gn) = r0;
            }
            if (m0 + m + 8 < M) {
                float2 r1 = make_float2(acc[sm][j][2] + b0, acc[sm][j][3] + b1);
                *(float2*)(C + (size_t)(m0 + m + 8) * N_ + gn) = r1;
            }
        }
    }

    if (SCORE) {
        __syncthreads();
        if (tid < 128 && m0 + tid < M) sout[m0 + tid] = s_red[tid];
    }
}

// ---------------------------------------------------------------------------
// edge: warp per edge; gather psrc[si[si[e]]], vector-atomic into num[ti[e]]
// ---------------------------------------------------------------------------
__global__ __launch_bounds__(256) void edge_kernel(
    const int* __restrict__ si, const int* __restrict__ ti,
    const float* __restrict__ sp, const float* __restrict__ ssrc,
    const float* __restrict__ stgt, float* __restrict__ num,
    float* __restrict__ den)
{
    int w = (blockIdx.x * blockDim.x + threadIdx.x) >> 5;
    if (w >= EE) return;
    int lane = threadIdx.x & 31;

    int s1 = __ldg(si + w);
    int t  = __ldg(ti + w);
    int s2 = __ldg(si + s1);              // reference quirk: src[si][si]

    float lg  = __ldg(ssrc + s2) + __ldg(stgt + t);
    float lr  = lg > 0.f ? lg : 0.2f * lg;
    float att = __expf(lr);

    float4 v = __ldg((const float4*)(sp + (size_t)s2 * HH) + lane);
    float4 r = make_float4(v.x * att, v.y * att, v.z * att, v.w * att);

    float* np = num + (size_t)t * HH + lane * 4;
    asm volatile("red.global.add.v4.f32 [%0], {%1,%2,%3,%4};"
                 :: "l"(np), "f"(r.x), "f"(r.y), "f"(r.z), "f"(r.w)
                 : "memory");
    if (lane == 0) atomicAdd(den + t, att);
}

// ---------------------------------------------------------------------------
// combine: out = relu(ptgt + num / (den + eps))
// ---------------------------------------------------------------------------
__global__ __launch_bounds__(256) void combine_kernel(
    const float* __restrict__ tp, const float* __restrict__ num,
    const float* __restrict__ den, float* __restrict__ of)
{
    int i = blockIdx.x * blockDim.x + threadIdx.x;   // float4 index
    if (i >= NN * (HH / 4)) return;
    int row = i / (HH / 4);
    float invd = 1.f / (den[row] + 1e-6f);
    float4 t = __ldg((const float4*)tp + i);
    float4 n = ((const float4*)num)[i];
    float4 r;
    r.x = fmaxf(fmaf(n.x, invd, t.x), 0.f);
    r.y = fmaxf(fmaf(n.y, invd, t.y), 0.f);
    r.z = fmaxf(fmaf(n.z, invd, t.z), 0.f);
    r.w = fmaxf(fmaf(n.w, invd, t.w), 0.f);
    ((float4*)of)[i] = r;
}

// ---------------------------------------------------------------------------
extern "C" void kernel_launch(void* const* d_in, const int* in_sizes, int n_in,
                              void* d_out, int out_size)
{
    const float* x_user     = (const float*)d_in[0];
    const float* x_spot     = (const float*)d_in[1];
    const int*   e_us       = (const int*)d_in[2];
    const int*   e_su       = (const int*)d_in[3];
    const float* Ws_us0     = (const float*)d_in[4];
    const float* Wt_us0     = (const float*)d_in[5];
    const float* a_us0      = (const float*)d_in[6];
    const float* Ws_su0     = (const float*)d_in[7];
    const float* Wt_su0     = (const float*)d_in[8];
    const float* a_su0      = (const float*)d_in[9];
    const float* Ws_us1     = (const float*)d_in[10];
    const float* Wt_us1     = (const float*)d_in[11];
    const float* a_us1      = (const float*)d_in[12];
    const float* Ws_su1     = (const float*)d_in[13];
    const float* Wt_su1     = (const float*)d_in[14];
    const float* a_su1      = (const float*)d_in[15];
    const float* W_out_user = (const float*)d_in[16];
    const float* b_out_user = (const float*)d_in[17];
    const float* W_out_spot = (const float*)d_in[18];
    const float* b_out_spot = (const float*)d_in[19];

    float* base = nullptr;
    cudaGetSymbolAddress((void**)&base, g_scratch);

    float* pu    = base + 0ull * NH;
    float* pts   = base + 1ull * NH;
    float* ps    = base + 2ull * NH;
    float* ptu   = base + 3ull * NH;
    float* num_s = base + 4ull * NH;
    float* num_u = base + 5ull * NH;
    float* h_u   = base + 6ull * NH;
    float* h_s   = base + 7ull * NH;
    float* den_s = base + 8ull * NH;
    float* den_u = den_s + NN;
    float* s_src = den_u + NN;
    float* s_tgt = s_src + NN;
    float* wt    = den_s + 6ull * NN;     // split weights (bf16, viewed as floats)

    // weight slots (float-count sized; stores hi then lo bf16 arrays)
    auto bfp = [](float* p) { return (__nv_bfloat16*)p; };
    float* w_ws_us0 = wt;                 wt += 64 * 128;    // 2 bf16 halves = K*N*4B
    float* w_wt_us0 = wt;                 wt += 64 * 128;
    float* w_ws_su0 = wt;                 wt += 64 * 128;
    float* w_wt_su0 = wt;                 wt += 64 * 128;
    float* w_ws_us1 = wt;                 wt += 128 * 128;
    float* w_wt_us1 = wt;                 wt += 128 * 128;
    float* w_ws_su1 = wt;                 wt += 128 * 128;
    float* w_wt_su1 = wt;                 wt += 128 * 128;
    float* w_out_u  = wt;                 wt += 128 * 64;
    float* w_out_s  = wt;

    float* out  = (float*)d_out;
    float* o_xu = out;
    float* o_xs = out + (size_t)NH;
    float* o_u  = out + 2ull * NH;
    float* o_s  = o_u + (size_t)NN * 64;

    const int GEMM_GRID = (NN + 127) / 128;
    const int ELT_GRID  = NN * (HH / 4) / 256;
    const int EDGE_GRID = EE * 32 / 256;

    // dynamic smem sizes
    constexpr int SM_128_64  = (2 * 128 * 72 + 2 * 128 * 72) * 2 + 512;   // 74240
    constexpr int SM_128_128 = (2 * 128 * 136 + 2 * 128 * 136) * 2 + 512; // 139776
    constexpr int SM_64_128  = (2 * 128 * 136 + 2 * 64 * 136) * 2 + 512;  // 104960
    cudaFuncSetAttribute((const void*)gemm_mma<128, 64, true, false>,
                         cudaFuncAttributeMaxDynamicSharedMemorySize, SM_128_64);
    cudaFuncSetAttribute((const void*)gemm_mma<128, 128, true, false>,
                         cudaFuncAttributeMaxDynamicSharedMemorySize, SM_128_128);
    cudaFuncSetAttribute((const void*)gemm_mma<64, 128, false, true>,
                         cudaFuncAttributeMaxDynamicSharedMemorySize, SM_64_128);

    // ---- preprocess weights (transpose + bf16 split) ----
    auto prep = [&](const float* W, float* slot, int K, int N) {
        int tot = K * N;
        prep_w_kernel<<<(tot + 255) / 256, 256>>>(W, bfp(slot), bfp(slot) + tot, K, N);
    };
    prep(Ws_us0, w_ws_us0, 64, 128);  prep(Wt_us0, w_wt_us0, 64, 128);
    prep(Ws_su0, w_ws_su0, 64, 128);  prep(Wt_su0, w_wt_su0, 64, 128);
    prep(Ws_us1, w_ws_us1, 128, 128); prep(Wt_us1, w_wt_us1, 128, 128);
    prep(Ws_su1, w_ws_su1, 128, 128); prep(Wt_su1, w_wt_su1, 128, 128);
    prep(W_out_user, w_out_u, 128, 64);
    prep(W_out_spot, w_out_s, 128, 64);

    auto conv = [&](const float* xsrc, const float* xtgt,
                    float* Wsrc, float* Wtgt, const float* a,
                    const int* si, const int* ti,
                    float* psrc, float* ptgt, float* num, float* den,
                    float* outf, int K) {
        if (K == 64) {
            gemm_mma<128, 64, true, false><<<GEMM_GRID, 256, SM_128_64>>>(
                xsrc, bfp(Wsrc), bfp(Wsrc) + 64 * 128, nullptr, a, psrc, s_src, NN);
            gemm_mma<128, 64, true, false><<<GEMM_GRID, 256, SM_128_64>>>(
                xtgt, bfp(Wtgt), bfp(Wtgt) + 64 * 128, nullptr, a + HH, ptgt, s_tgt, NN);
        } else {
            gemm_mma<128, 128, true, false><<<GEMM_GRID, 256, SM_128_128>>>(
                xsrc, bfp(Wsrc), bfp(Wsrc) + 128 * 128, nullptr, a, psrc, s_src, NN);
            gemm_mma<128, 128, true, false><<<GEMM_GRID, 256, SM_128_128>>>(
                xtgt, bfp(Wtgt), bfp(Wtgt) + 128 * 128, nullptr, a + HH, ptgt, s_tgt, NN);
        }
        edge_kernel<<<EDGE_GRID, 256>>>(si, ti, psrc, s_src, s_tgt, num, den);
        combine_kernel<<<ELT_GRID, 256>>>(ptgt, num, den, outf);
    };

    // -------- layer 0 (K = 64) --------
    cudaMemsetAsync(num_s, 0, 2ull * NH * sizeof(float), 0);
    cudaMemsetAsync(den_s, 0, 2ull * NN * sizeof(float), 0);
    conv(x_user, x_spot, w_ws_us0, w_wt_us0, a_us0, e_us, e_us + EE,
         pu, pts, num_s, den_s, h_s, 64);
    conv(x_spot, x_user, w_ws_su0, w_wt_su0, a_su0, e_su, e_su + EE,
         ps, ptu, num_u, den_u, h_u, 64);

    // -------- layer 1 (K = 128) --------
    cudaMemsetAsync(num_s, 0, 2ull * NH * sizeof(float), 0);
    cudaMemsetAsync(den_s, 0, 2ull * NN * sizeof(float), 0);
    conv(h_u, h_s, w_ws_us1, w_wt_us1, a_us1, e_us, e_us + EE,
         pu, pts, num_s, den_s, o_xs, 128);
    conv(h_s, h_u, w_ws_su1, w_wt_su1, a_su1, e_su, e_su + EE,
         ps, ptu, num_u, den_u, o_xu, 128);

    // -------- final per-type linear (N = 64, bias) --------
    gemm_mma<64, 128, false, true><<<GEMM_GRID, 256, SM_64_128>>>(
        o_xu, bfp(w_out_u), bfp(w_out_u) + 128 * 64, b_out_user, nullptr, o_u, nullptr, NN);
    gemm_mma<64, 128, false, true><<<GEMM_GRID, 256, SM_64_128>>>(
        o_xs, bfp(w_out_s), bfp(w_out_s) + 128 * 64, b_out_spot, nullptr, o_s, nullptr, NN);
}